// round 8
// baseline (speedup 1.0000x reference)
#include <cuda_runtime.h>
#include <cuda_fp16.h>
#include <float.h>
#include <math.h>
#include <stdint.h>

// Problem constants
#define B_    8
#define NPTS  8192
#define NS    2048
#define D1    128
#define D2    256
#define C1    384      // D1 + D2
#define C2    256
#define C3    128
#define MTOT  (B_ * NPTS)   // 65536
#define GRIDX (MTOT / 128)  // 512 column blocks per GEMM

// ---------------------------------------------------------------------------
// Scratch (static device globals — no allocations allowed)
// ---------------------------------------------------------------------------
__device__ __align__(16) uint32_t g_interpP[(size_t)(D2 / 2) * MTOT]; // 32 MB half2 k-pairs [cpair][m]
__device__ float  g_h1[(size_t)C2 * MTOT];       // 64 MB  GEMM1 out (pre-BN) [c][m]
__device__ float  g_h2[(size_t)C3 * MTOT];       // 32 MB  GEMM2 out (pre-BN) [c][m]
__device__ float  g_sfT[(size_t)B_ * NS * D2];   // 16 MB  sfeat transposed [b][s][c]
__device__ float4 g_w[MTOT];                     // per-point 3-NN weights
__device__ int4   g_i[MTOT];                     // per-point 3-NN indices
__device__ float2 g_ss1[C2];                     // BN1 (scale, shift)
__device__ float2 g_ss2[C3];                     // BN2 (scale, shift)
__device__ __align__(16) __half g_W1h[C2 * C1];  // fp16 weights, row-major
__device__ __align__(16) __half g_W2h[C3 * C2];
// per-block BN partial stats (deterministic two-stage reduction, no atomics)
__device__ float g_psA[C2 * GRIDX], g_pqA[C2 * GRIDX];
__device__ float g_psB[C3 * GRIDX], g_pqB[C3 * GRIDX];

__device__ __forceinline__ void mma16816(float* d, const uint32_t* a, const uint32_t* b) {
    asm volatile(
        "mma.sync.aligned.m16n8k16.row.col.f32.f16.f16.f32 "
        "{%0,%1,%2,%3}, {%4,%5,%6,%7}, {%8,%9}, {%0,%1,%2,%3};\n"
        : "+f"(d[0]), "+f"(d[1]), "+f"(d[2]), "+f"(d[3])
        : "r"(a[0]), "r"(a[1]), "r"(a[2]), "r"(a[3]), "r"(b[0]), "r"(b[1]));
}

// ---------------------------------------------------------------------------
// Kernel 0: convert weights to fp16
// ---------------------------------------------------------------------------
__global__ void __launch_bounds__(256) prep_weights_kernel(
    const float* __restrict__ W1, const float* __restrict__ W2)
{
    int i = blockIdx.x * 256 + threadIdx.x;
    if (i < C2 * C1) g_W1h[i] = __float2half_rn(W1[i]);
    if (i < C3 * C2) g_W2h[i] = __float2half_rn(W2[i]);
}

// ---------------------------------------------------------------------------
// Kernel 1: 3-NN search, 2 points per thread (smem load amortized)
//   128 threads/block, 256 points/block, 256 blocks.
// ---------------------------------------------------------------------------
__global__ void __launch_bounds__(128) knn_kernel(
    const float* __restrict__ pp,     // [B,3,N]
    const float* __restrict__ spp)    // [B,3,S]
{
    __shared__ float4 ssmp[NS];       // 32 KB

    const int b   = blockIdx.x >> 5;           // 32 blocks per batch
    const int n0  = (blockIdx.x & 31) << 8;    // 256 points per block
    const int tid = threadIdx.x;

    const float* sb = spp + (size_t)b * 3 * NS;
    for (int s = tid; s < NS; s += 128) {
        float x = sb[s], y = sb[s + NS], z = sb[s + 2 * NS];
        ssmp[s] = make_float4(x, y, z, fmaf(x, x, fmaf(y, y, z * z)));
    }
    __syncthreads();

    const int nA = n0 + tid, nB = nA + 128;
    const float* pb = pp + (size_t)b * 3 * NPTS;
    const float ax = pb[nA], ay = pb[nA + NPTS], az = pb[nA + 2 * NPTS];
    const float bx = pb[nB], by = pb[nB + NPTS], bz = pb[nB + 2 * NPTS];

    float ad0 = FLT_MAX, ad1 = FLT_MAX, ad2 = FLT_MAX;
    float bd0 = FLT_MAX, bd1 = FLT_MAX, bd2 = FLT_MAX;
    int   ai0 = 0, ai1 = 0, ai2 = 0, bi0 = 0, bi1 = 0, bi2 = 0;

    #pragma unroll 4
    for (int j = 0; j < NS; j++) {
        float4 q  = ssmp[j];
        float sA = fmaf(-2.0f, fmaf(ax, q.x, fmaf(ay, q.y, az * q.z)), q.w);
        float sB = fmaf(-2.0f, fmaf(bx, q.x, fmaf(by, q.y, bz * q.z)), q.w);
        if (sA < ad2) {
            if (sA < ad1) {
                ad2 = ad1; ai2 = ai1;
                if (sA < ad0) { ad1 = ad0; ai1 = ai0; ad0 = sA; ai0 = j; }
                else          { ad1 = sA; ai1 = j; }
            } else { ad2 = sA; ai2 = j; }
        }
        if (sB < bd2) {
            if (sB < bd1) {
                bd2 = bd1; bi2 = bi1;
                if (sB < bd0) { bd1 = bd0; bi1 = bi0; bd0 = sB; bi0 = j; }
                else          { bd1 = sB; bi1 = j; }
            } else { bd2 = sB; bi2 = j; }
        }
    }

    {
        const float p2 = fmaf(ax, ax, fmaf(ay, ay, az * az));
        float a0 = 1.0f / ((ad0 + p2) + 1e-8f);
        float a1 = 1.0f / ((ad1 + p2) + 1e-8f);
        float a2 = 1.0f / ((ad2 + p2) + 1e-8f);
        float inv = 1.0f / (a0 + a1 + a2);
        g_w[b * NPTS + nA] = make_float4(a0 * inv, a1 * inv, a2 * inv, 0.0f);
        g_i[b * NPTS + nA] = make_int4(ai0, ai1, ai2, 0);
    }
    {
        const float p2 = fmaf(bx, bx, fmaf(by, by, bz * bz));
        float a0 = 1.0f / ((bd0 + p2) + 1e-8f);
        float a1 = 1.0f / ((bd1 + p2) + 1e-8f);
        float a2 = 1.0f / ((bd2 + p2) + 1e-8f);
        float inv = 1.0f / (a0 + a1 + a2);
        g_w[b * NPTS + nB] = make_float4(a0 * inv, a1 * inv, a2 * inv, 0.0f);
        g_i[b * NPTS + nB] = make_int4(bi0, bi1, bi2, 0);
    }
}

// ---------------------------------------------------------------------------
// Kernel 1b: transpose sfeat [b][c][s] -> g_sfT [b][s][c]
// ---------------------------------------------------------------------------
__global__ void __launch_bounds__(256) transpose_sfeat_kernel(
    const float* __restrict__ sfeat)
{
    __shared__ float tile[32][33];
    const int b  = blockIdx.z;
    const int s0 = blockIdx.x * 32;
    const int c0 = blockIdx.y * 32;
    const int tx = threadIdx.x;
    const int ty = threadIdx.y;

    #pragma unroll
    for (int r = 0; r < 32; r += 8)
        tile[ty + r][tx] = sfeat[((size_t)b * D2 + c0 + ty + r) * NS + s0 + tx];
    __syncthreads();
    #pragma unroll
    for (int r = 0; r < 32; r += 8)
        g_sfT[((size_t)b * NS + s0 + ty + r) * D2 + c0 + tx] = tile[tx][ty + r];
}

// ---------------------------------------------------------------------------
// Kernel 2: interpolation -> g_interpP, half2 (c even, c odd) k-pair packed.
//   Identical rounding to the old loader-side conversion, just moved earlier.
// ---------------------------------------------------------------------------
__global__ void __launch_bounds__(256) interp_kernel()
{
    __shared__ float  st[D2][33];
    __shared__ float4 sw[32];
    __shared__ int4   si[32];

    const int m0  = blockIdx.x * 32;
    const int b   = m0 / NPTS;
    const int tid = threadIdx.x;

    if (tid < 32) { sw[tid] = g_w[m0 + tid]; si[tid] = g_i[m0 + tid]; }
    __syncthreads();

    const float* fT = g_sfT + (size_t)b * NS * D2;
    #pragma unroll 8
    for (int p = 0; p < 32; p++) {
        float4 w = sw[p];
        int4   ii = si[p];
        float v = fmaf(w.x, __ldg(fT + (size_t)ii.x * D2 + tid),
                  fmaf(w.y, __ldg(fT + (size_t)ii.y * D2 + tid),
                       w.z * __ldg(fT + (size_t)ii.z * D2 + tid)));
        st[tid][p] = v;
    }
    __syncthreads();

    const int cpb = tid >> 3;         // 0..31
    const int j   = (tid & 7) << 2;   // 0,4,...,28
    #pragma unroll
    for (int r = 0; r < 4; r++) {
        int cp = r * 32 + cpb;        // 0..127
        uint32_t v[4];
        #pragma unroll
        for (int e = 0; e < 4; e++) {
            __half2 h = __floats2half2_rn(st[2 * cp][j + e], st[2 * cp + 1][j + e]);
            v[e] = *reinterpret_cast<uint32_t*>(&h);
        }
        *(uint4*)&g_interpP[(size_t)cp * MTOT + m0 + j] = *(uint4*)v;
    }
}

// ---------------------------------------------------------------------------
// Kernel 3: fp16 tensor-core GEMM, 3-stage software pipeline.
//   C[i][j] = sum_k W[i][k] * Bsrc[k][j]
//   128x128 tile, BK=16, 8 warps (2x4), warp tile 64x32, mma.m16n8k16 f16.
//   Two register prefetch sets in flight -> each LDG gets ~2 k-steps of cover.
//   B is packed to half2 k-pairs at LDG time (interp path: direct uint4 copy).
//   Epilogue emits per-block per-channel (sum, sumsq) BN partials.
// ---------------------------------------------------------------------------
__global__ void __launch_bounds__(256, 2) mma_gemm_kernel(
    const float* __restrict__ skip,   // mode 1 only
    int K, int mode)
{
    __shared__ uint32_t As[2][128 * 8];   // [m][kpair]
    __shared__ uint32_t Bs[2][8 * 128];   // [kpair][n ^ (kp<<3)]

    const __half* __restrict__ Wh = (mode == 1) ? g_W1h : g_W2h;

    const int tid  = threadIdx.x;
    const int lane = tid & 31;
    const int wid  = tid >> 5;
    const int wm   = wid >> 2;
    const int wn   = wid & 3;
    const int g    = lane >> 2;
    const int t    = lane & 3;

    const int j0 = blockIdx.x * 128;
    const int i0 = blockIdx.y * 128;

    const int arow = tid >> 1;
    const int akh  = tid & 1;
    const int brp  = tid >> 5;
    const int bc0  = lane * 4;

    const int bb  = j0 / NPTS;
    const int nn0 = j0 % NPTS;

    float acc[4][4][4];
    #pragma unroll
    for (int mt = 0; mt < 4; mt++)
        #pragma unroll
        for (int nt = 0; nt < 4; nt++)
            #pragma unroll
            for (int e = 0; e < 4; e++) acc[mt][nt][e] = 0.0f;

    #define PACK_BNRELU(PH, rb0, rb1, q0, q1)                                    \
    {                                                                            \
        const float* x0 = &rb0.x; const float* x1 = &rb1.x;                      \
        _Pragma("unroll")                                                        \
        for (int e = 0; e < 4; e++) {                                            \
            float u0 = fmaxf(fmaf(x0[e], q0.x, q0.y), 0.0f);                     \
            float u1 = fmaxf(fmaf(x1[e], q1.x, q1.y), 0.0f);                     \
            __half2 h = __floats2half2_rn(u0, u1);                               \
            PH[e] = *reinterpret_cast<uint32_t*>(&h);                            \
        }                                                                        \
    }

    #define LDG_TILE(kt, RA, PH)                                                 \
    {                                                                            \
        RA = *(const uint4*)(Wh + (size_t)(i0 + arow) * K + (kt) + akh * 8);     \
        int k0 = (kt) + brp * 2;                                                 \
        if (mode == 1) {                                                         \
            if (k0 < D1) {                                                       \
                const float* s0 = skip + ((size_t)bb * D1 + k0) * NPTS + nn0 + bc0; \
                float4 rb0 = *(const float4*)s0;                                 \
                float4 rb1 = *(const float4*)(s0 + NPTS);                        \
                const float* y0 = &rb0.x; const float* y1 = &rb1.x;              \
                _Pragma("unroll")                                                \
                for (int e = 0; e < 4; e++) {                                    \
                    __half2 h = __floats2half2_rn(y0[e], y1[e]);                 \
                    PH[e] = *reinterpret_cast<uint32_t*>(&h);                    \
                }                                                                \
            } else {                                                             \
                int cp = (k0 - D1) >> 1;                                         \
                *(uint4*)PH = *(const uint4*)&g_interpP[(size_t)cp * MTOT + j0 + bc0]; \
            }                                                                    \
        } else {                                                                 \
            const float* s0 = g_h1 + (size_t)k0 * MTOT + j0 + bc0;               \
            float4 rb0 = *(const float4*)s0;                                     \
            float4 rb1 = *(const float4*)(s0 + MTOT);                            \
            float2 q0 = g_ss1[k0], q1 = g_ss1[k0 + 1];                           \
            PACK_BNRELU(PH, rb0, rb1, q0, q1);                                   \
        }                                                                        \
    }

    #define STS_TILE(buf, RA, PH)                                               \
    {                                                                            \
        *(uint4*)&As[buf][arow * 8 + akh * 4] = RA;                              \
        int col = bc0 ^ (brp << 3);                                              \
        *(uint4*)&Bs[buf][brp * 128 + col] = *(uint4*)PH;                        \
    }

    #define COMPUTE(buf)                                                         \
    {                                                                            \
        uint32_t bf[4][2];                                                       \
        _Pragma("unroll")                                                        \
        for (int nt = 0; nt < 4; nt++) {                                         \
            int n = wn * 32 + nt * 8 + g;                                        \
            bf[nt][0] = Bs[buf][t * 128 + (n ^ (t << 3))];                       \
            bf[nt][1] = Bs[buf][(t + 4) * 128 + (n ^ ((t + 4) << 3))];           \
        }                                                                        \
        _Pragma("unroll")                                                        \
        for (int mt = 0; mt < 4; mt++) {                                         \
            int r = wm * 64 + mt * 16 + g;                                       \
            uint32_t ah[4];                                                      \
            ah[0] = As[buf][r * 8 + t];                                          \
            ah[1] = As[buf][(r + 8) * 8 + t];                                    \
            ah[2] = As[buf][r * 8 + t + 4];                                      \
            ah[3] = As[buf][(r + 8) * 8 + t + 4];                                \
            _Pragma("unroll")                                                    \
            for (int nt = 0; nt < 4; nt++)                                       \
                mma16816(acc[mt][nt], ah, bf[nt]);                               \
        }                                                                        \
    }

    uint4 rA0, rA1;
    uint32_t pB0[4], pB1[4];

    LDG_TILE(0,  rA0, pB0);
    LDG_TILE(16, rA1, pB1);
    STS_TILE(0, rA0, pB0);
    __syncthreads();

    int buf = 0;
    for (int kt = 32; kt < K; kt += 16) {
        LDG_TILE(kt, rA0, pB0);          // 2 k-steps ahead
        COMPUTE(buf);
        STS_TILE(buf ^ 1, rA1, pB1);     // 1 k-step ahead
        __syncthreads();
        buf ^= 1;
        rA1 = rA0;
        pB1[0] = pB0[0]; pB1[1] = pB0[1]; pB1[2] = pB0[2]; pB1[3] = pB0[3];
    }
    COMPUTE(buf);
    STS_TILE(buf ^ 1, rA1, pB1);
    __syncthreads();
    COMPUTE(buf ^ 1);

    // ---- store C tile ----
    float* dst = (mode == 1) ? g_h1 : g_h2;
    #pragma unroll
    for (int mt = 0; mt < 4; mt++) {
        #pragma unroll
        for (int nt = 0; nt < 4; nt++) {
            int row = i0 + wm * 64 + mt * 16 + g;
            int col = j0 + wn * 32 + nt * 8 + 2 * t;
            *(float2*)&dst[(size_t)row * MTOT + col] =
                make_float2(acc[mt][nt][0], acc[mt][nt][1]);
            *(float2*)&dst[(size_t)(row + 8) * MTOT + col] =
                make_float2(acc[mt][nt][2], acc[mt][nt][3]);
        }
    }

    // ---- per-block BN partial stats ----
    __syncthreads();
    float* Ssum = (float*)As;
    float* Ssq  = (float*)Bs;
    const int ci = wn * 4 + t;
    #pragma unroll
    for (int mt = 0; mt < 4; mt++) {
        int r0 = wm * 64 + mt * 16 + g;
        float s0 = 0.f, q0 = 0.f, s1 = 0.f, q1 = 0.f;
        #pragma unroll
        for (int nt = 0; nt < 4; nt++) {
            float e0 = acc[mt][nt][0], e1 = acc[mt][nt][1];
            float e2 = acc[mt][nt][2], e3 = acc[mt][nt][3];
            s0 += e0 + e1;  q0 += e0 * e0 + e1 * e1;
            s1 += e2 + e3;  q1 += e2 * e2 + e3 * e3;
        }
        Ssum[ci * 128 + r0]     = s0;  Ssq[ci * 128 + r0]     = q0;
        Ssum[ci * 128 + r0 + 8] = s1;  Ssq[ci * 128 + r0 + 8] = q1;
    }
    __syncthreads();

    float* psum = (mode == 1) ? g_psA : g_psB;
    float* psq  = (mode == 1) ? g_pqA : g_pqB;
    if (tid < 128) {
        float s = 0.f;
        #pragma unroll
        for (int c = 0; c < 16; c++) s += Ssum[c * 128 + tid];
        psum[(size_t)(i0 + tid) * GRIDX + blockIdx.x] = s;
    } else {
        int r = tid - 128;
        float q = 0.f;
        #pragma unroll
        for (int c = 0; c < 16; c++) q += Ssq[c * 128 + r];
        psq[(size_t)(i0 + r) * GRIDX + blockIdx.x] = q;
    }
    #undef LDG_TILE
    #undef STS_TILE
    #undef COMPUTE
    #undef PACK_BNRELU
}

// ---------------------------------------------------------------------------
// Kernel 4: reduce per-block partials -> per-channel (scale, shift).
// ---------------------------------------------------------------------------
__global__ void __launch_bounds__(256) bn_reduce_kernel(
    const float* __restrict__ g, const float* __restrict__ beta, int which)
{
    const int c   = blockIdx.x;
    const int tid = threadIdx.x;
    const float* ps = (which == 1) ? g_psA : g_psB;
    const float* pq = (which == 1) ? g_pqA : g_pqB;

    double s = (double)ps[(size_t)c * GRIDX + tid] + (double)ps[(size_t)c * GRIDX + tid + 256];
    double q = (double)pq[(size_t)c * GRIDX + tid] + (double)pq[(size_t)c * GRIDX + tid + 256];

    __shared__ double r1[256], r2[256];
    r1[tid] = s;  r2[tid] = q;
    __syncthreads();
    for (int o = 128; o > 0; o >>= 1) {
        if (tid < o) { r1[tid] += r1[tid + o]; r2[tid] += r2[tid + o]; }
        __syncthreads();
    }
    if (tid == 0) {
        double mean = r1[0] / (double)MTOT;
        double var  = r2[0] / (double)MTOT - mean * mean;
        double rs   = 1.0 / sqrt(var + 1e-5);
        float scale = (float)((double)g[c] * rs);
        float shift = (float)((double)beta[c] - mean * (double)g[c] * rs);
        if (which == 1) g_ss1[c] = make_float2(scale, shift);
        else            g_ss2[c] = make_float2(scale, shift);
    }
}

// ---------------------------------------------------------------------------
// Kernel 5: final BN2 + ReLU + layout transform [c][b*N+n] -> [b][c][n]
// ---------------------------------------------------------------------------
__global__ void __launch_bounds__(256) bn_out_kernel(float* __restrict__ out)
{
    size_t f = (size_t)blockIdx.x * blockDim.x + threadIdx.x;
    size_t e = f * 4;
    int c = (int)(e / MTOT);
    int m = (int)(e % MTOT);
    int b = m / NPTS;
    int n = m % NPTS;

    float4 v = ((const float4*)g_h2)[f];
    float2 ss = g_ss2[c];
    v.x = fmaxf(fmaf(v.x, ss.x, ss.y), 0.0f);
    v.y = fmaxf(fmaf(v.y, ss.x, ss.y), 0.0f);
    v.z = fmaxf(fmaf(v.z, ss.x, ss.y), 0.0f);
    v.w = fmaxf(fmaf(v.w, ss.x, ss.y), 0.0f);
    *(float4*)(out + ((size_t)b * C3 + c) * NPTS + n) = v;
}

// ---------------------------------------------------------------------------
// Launcher
// ---------------------------------------------------------------------------
extern "C" void kernel_launch(void* const* d_in, const int* in_sizes, int n_in,
                              void* d_out, int out_size)
{
    const float* pp    = (const float*)d_in[0];
    const float* spp   = (const float*)d_in[1];
    const float* skip  = (const float*)d_in[2];
    const float* sfeat = (const float*)d_in[3];
    const float* W1    = (const float*)d_in[4];
    // d_in[5] = b1 (cancels inside BN)
    const float* g1    = (const float*)d_in[6];
    const float* be1   = (const float*)d_in[7];
    const float* W2    = (const float*)d_in[8];
    // d_in[9] = b2 (cancels inside BN)
    const float* g2    = (const float*)d_in[10];
    const float* be2   = (const float*)d_in[11];
    float* out = (float*)d_out;

    prep_weights_kernel<<<(C2 * C1 + 255) / 256, 256>>>(W1, W2);

    knn_kernel<<<B_ * (NPTS / 256), 128>>>(pp, spp);
    {
        dim3 grid(NS / 32, D2 / 32, B_), blk(32, 8);
        transpose_sfeat_kernel<<<grid, blk>>>(sfeat);
    }

    interp_kernel<<<MTOT / 32, 256>>>();

    {   // GEMM1 (+BN1 partials): H1 = W1 @ [skip ; interp]
        dim3 grid(GRIDX, C2 / 128);
        mma_gemm_kernel<<<grid, 256>>>(skip, C1, 1);
    }
    bn_reduce_kernel<<<C2, 256>>>(g1, be1, 1);

    {   // GEMM2 (+BN2 partials): H2 = W2 @ relu(BN1(H1))
        dim3 grid(GRIDX, C3 / 128);
        mma_gemm_kernel<<<grid, 256>>>(nullptr, C2, 2);
    }
    bn_reduce_kernel<<<C3, 256>>>(g2, be2, 2);

    bn_out_kernel<<<(C3 * MTOT / 4) / 256, 256>>>(out);
}

// round 9
// speedup vs baseline: 1.0468x; 1.0468x over previous
#include <cuda_runtime.h>
#include <cuda_fp16.h>
#include <float.h>
#include <math.h>
#include <stdint.h>

// Problem constants
#define B_    8
#define NPTS  8192
#define NS    2048
#define D1    128
#define D2    256
#define C1    384      // D1 + D2
#define C2    256
#define C3    128
#define MTOT  (B_ * NPTS)   // 65536
#define GRIDX (MTOT / 128)  // 512 column blocks per GEMM

// ---------------------------------------------------------------------------
// Scratch (static device globals — no allocations allowed)
// ---------------------------------------------------------------------------
// Unified GEMM1 B operand, half2 k-pairs [cpair][m]: rows 0..63 = skip,
// rows 64..191 = interpolated features. 48 MB.
__device__ __align__(16) uint32_t g_BP1[(size_t)(C1 / 2) * MTOT];
__device__ float  g_h1[(size_t)C2 * MTOT];       // 64 MB GEMM1 out (pre-BN) [c][m]
__device__ float  g_h2[(size_t)C3 * MTOT];       // 32 MB GEMM2 out (pre-BN) [c][m]
__device__ float  g_sfT[(size_t)B_ * NS * D2];   // 16 MB sfeat transposed [b][s][c]
__device__ float4 g_w[MTOT];                     // per-point 3-NN weights
__device__ int4   g_i[MTOT];                     // per-point 3-NN indices
__device__ float2 g_ss1[C2];                     // BN1 (scale, shift)
__device__ float2 g_ss2[C3];                     // BN2 (scale, shift)
__device__ __align__(16) __half g_W1h[C2 * C1];  // fp16 weights, row-major
__device__ __align__(16) __half g_W2h[C3 * C2];
// per-block BN partial stats (deterministic two-stage reduction, no atomics)
__device__ float g_psA[C2 * GRIDX], g_pqA[C2 * GRIDX];
__device__ float g_psB[C3 * GRIDX], g_pqB[C3 * GRIDX];

__device__ __forceinline__ void mma16816(float* d, const uint32_t* a, const uint32_t* b) {
    asm volatile(
        "mma.sync.aligned.m16n8k16.row.col.f32.f16.f16.f32 "
        "{%0,%1,%2,%3}, {%4,%5,%6,%7}, {%8,%9}, {%0,%1,%2,%3};\n"
        : "+f"(d[0]), "+f"(d[1]), "+f"(d[2]), "+f"(d[3])
        : "r"(a[0]), "r"(a[1]), "r"(a[2]), "r"(a[3]), "r"(b[0]), "r"(b[1]));
}

__device__ __forceinline__ void cp_async16(uint32_t smem_addr, const void* gptr) {
    asm volatile("cp.async.ca.shared.global [%0], [%1], 16;\n"
                 :: "r"(smem_addr), "l"(gptr));
}
#define CP_COMMIT()  asm volatile("cp.async.commit_group;\n")
#define CP_WAIT(N)   asm volatile("cp.async.wait_group %0;\n" :: "n"(N))

// ---------------------------------------------------------------------------
// Kernel 0: convert weights to fp16
// ---------------------------------------------------------------------------
__global__ void __launch_bounds__(256) prep_weights_kernel(
    const float* __restrict__ W1, const float* __restrict__ W2)
{
    int i = blockIdx.x * 256 + threadIdx.x;
    if (i < C2 * C1) g_W1h[i] = __float2half_rn(W1[i]);
    if (i < C3 * C2) g_W2h[i] = __float2half_rn(W2[i]);
}

// ---------------------------------------------------------------------------
// Kernel 0b: pack skip features into g_BP1 rows 0..63 (half2 channel pairs)
//   Same __floats2half2_rn rounding the GEMM1 loader used before.
// ---------------------------------------------------------------------------
__global__ void __launch_bounds__(256) pack_skip_kernel(
    const float* __restrict__ skip)   // [B, D1, N]
{
    const int cp = blockIdx.y;                       // 0..63
    const int m0 = (blockIdx.x * 256 + threadIdx.x) * 4;
    const int b  = m0 / NPTS;
    const int n  = m0 % NPTS;
    const float* r0 = skip + ((size_t)b * D1 + 2 * cp)     * NPTS + n;
    const float* r1 = skip + ((size_t)b * D1 + 2 * cp + 1) * NPTS + n;
    float4 v0 = *(const float4*)r0;
    float4 v1 = *(const float4*)r1;
    uint32_t p[4];
    const float* x0 = &v0.x; const float* x1 = &v1.x;
    #pragma unroll
    for (int e = 0; e < 4; e++) {
        __half2 h = __floats2half2_rn(x0[e], x1[e]);
        p[e] = *reinterpret_cast<uint32_t*>(&h);
    }
    *(uint4*)&g_BP1[(size_t)cp * MTOT + m0] = *(uint4*)p;
}

// ---------------------------------------------------------------------------
// Kernel 1: 3-NN search, 2 points per thread
// ---------------------------------------------------------------------------
__global__ void __launch_bounds__(128) knn_kernel(
    const float* __restrict__ pp,     // [B,3,N]
    const float* __restrict__ spp)    // [B,3,S]
{
    __shared__ float4 ssmp[NS];       // 32 KB

    const int b   = blockIdx.x >> 5;
    const int n0  = (blockIdx.x & 31) << 8;
    const int tid = threadIdx.x;

    const float* sb = spp + (size_t)b * 3 * NS;
    for (int s = tid; s < NS; s += 128) {
        float x = sb[s], y = sb[s + NS], z = sb[s + 2 * NS];
        ssmp[s] = make_float4(x, y, z, fmaf(x, x, fmaf(y, y, z * z)));
    }
    __syncthreads();

    const int nA = n0 + tid, nB = nA + 128;
    const float* pb = pp + (size_t)b * 3 * NPTS;
    const float ax = pb[nA], ay = pb[nA + NPTS], az = pb[nA + 2 * NPTS];
    const float bx = pb[nB], by = pb[nB + NPTS], bz = pb[nB + 2 * NPTS];

    float ad0 = FLT_MAX, ad1 = FLT_MAX, ad2 = FLT_MAX;
    float bd0 = FLT_MAX, bd1 = FLT_MAX, bd2 = FLT_MAX;
    int   ai0 = 0, ai1 = 0, ai2 = 0, bi0 = 0, bi1 = 0, bi2 = 0;

    #pragma unroll 4
    for (int j = 0; j < NS; j++) {
        float4 q  = ssmp[j];
        float sA = fmaf(-2.0f, fmaf(ax, q.x, fmaf(ay, q.y, az * q.z)), q.w);
        float sB = fmaf(-2.0f, fmaf(bx, q.x, fmaf(by, q.y, bz * q.z)), q.w);
        if (sA < ad2) {
            if (sA < ad1) {
                ad2 = ad1; ai2 = ai1;
                if (sA < ad0) { ad1 = ad0; ai1 = ai0; ad0 = sA; ai0 = j; }
                else          { ad1 = sA; ai1 = j; }
            } else { ad2 = sA; ai2 = j; }
        }
        if (sB < bd2) {
            if (sB < bd1) {
                bd2 = bd1; bi2 = bi1;
                if (sB < bd0) { bd1 = bd0; bi1 = bi0; bd0 = sB; bi0 = j; }
                else          { bd1 = sB; bi1 = j; }
            } else { bd2 = sB; bi2 = j; }
        }
    }

    {
        const float p2 = fmaf(ax, ax, fmaf(ay, ay, az * az));
        float a0 = 1.0f / ((ad0 + p2) + 1e-8f);
        float a1 = 1.0f / ((ad1 + p2) + 1e-8f);
        float a2 = 1.0f / ((ad2 + p2) + 1e-8f);
        float inv = 1.0f / (a0 + a1 + a2);
        g_w[b * NPTS + nA] = make_float4(a0 * inv, a1 * inv, a2 * inv, 0.0f);
        g_i[b * NPTS + nA] = make_int4(ai0, ai1, ai2, 0);
    }
    {
        const float p2 = fmaf(bx, bx, fmaf(by, by, bz * bz));
        float a0 = 1.0f / ((bd0 + p2) + 1e-8f);
        float a1 = 1.0f / ((bd1 + p2) + 1e-8f);
        float a2 = 1.0f / ((bd2 + p2) + 1e-8f);
        float inv = 1.0f / (a0 + a1 + a2);
        g_w[b * NPTS + nB] = make_float4(a0 * inv, a1 * inv, a2 * inv, 0.0f);
        g_i[b * NPTS + nB] = make_int4(bi0, bi1, bi2, 0);
    }
}

// ---------------------------------------------------------------------------
// Kernel 1b: transpose sfeat [b][c][s] -> g_sfT [b][s][c]
// ---------------------------------------------------------------------------
__global__ void __launch_bounds__(256) transpose_sfeat_kernel(
    const float* __restrict__ sfeat)
{
    __shared__ float tile[32][33];
    const int b  = blockIdx.z;
    const int s0 = blockIdx.x * 32;
    const int c0 = blockIdx.y * 32;
    const int tx = threadIdx.x;
    const int ty = threadIdx.y;

    #pragma unroll
    for (int r = 0; r < 32; r += 8)
        tile[ty + r][tx] = sfeat[((size_t)b * D2 + c0 + ty + r) * NS + s0 + tx];
    __syncthreads();
    #pragma unroll
    for (int r = 0; r < 32; r += 8)
        g_sfT[((size_t)b * NS + s0 + ty + r) * D2 + c0 + tx] = tile[tx][ty + r];
}

// ---------------------------------------------------------------------------
// Kernel 2: interpolation -> g_BP1 rows 64..191 (half2 channel-pair packed)
// ---------------------------------------------------------------------------
__global__ void __launch_bounds__(256) interp_kernel()
{
    __shared__ float  st[D2][33];
    __shared__ float4 sw[32];
    __shared__ int4   si[32];

    const int m0  = blockIdx.x * 32;
    const int b   = m0 / NPTS;
    const int tid = threadIdx.x;

    if (tid < 32) { sw[tid] = g_w[m0 + tid]; si[tid] = g_i[m0 + tid]; }
    __syncthreads();

    const float* fT = g_sfT + (size_t)b * NS * D2;
    #pragma unroll 8
    for (int p = 0; p < 32; p++) {
        float4 w = sw[p];
        int4   ii = si[p];
        float v = fmaf(w.x, __ldg(fT + (size_t)ii.x * D2 + tid),
                  fmaf(w.y, __ldg(fT + (size_t)ii.y * D2 + tid),
                       w.z * __ldg(fT + (size_t)ii.z * D2 + tid)));
        st[tid][p] = v;
    }
    __syncthreads();

    const int cpb = tid >> 3;         // 0..31
    const int j   = (tid & 7) << 2;   // 0,4,...,28
    #pragma unroll
    for (int r = 0; r < 4; r++) {
        int cp = r * 32 + cpb;        // 0..127
        uint32_t v[4];
        #pragma unroll
        for (int e = 0; e < 4; e++) {
            __half2 h = __floats2half2_rn(st[2 * cp][j + e], st[2 * cp + 1][j + e]);
            v[e] = *reinterpret_cast<uint32_t*>(&h);
        }
        *(uint4*)&g_BP1[(size_t)(64 + cp) * MTOT + m0 + j] = *(uint4*)v;
    }
}

// ---------------------------------------------------------------------------
// Shared MMA compute / epilogue fragments (identical layout in both GEMMs)
// ---------------------------------------------------------------------------
#define MMA_COMPUTE(ASBUF, BSBUF)                                             \
{                                                                             \
    uint32_t bf[4][2];                                                        \
    _Pragma("unroll")                                                         \
    for (int nt = 0; nt < 4; nt++) {                                          \
        int n = wn * 32 + nt * 8 + g;                                         \
        bf[nt][0] = (BSBUF)[t * 128 + (n ^ (t << 3))];                        \
        bf[nt][1] = (BSBUF)[(t + 4) * 128 + (n ^ ((t + 4) << 3))];            \
    }                                                                         \
    _Pragma("unroll")                                                         \
    for (int mt = 0; mt < 4; mt++) {                                          \
        int r = wm * 64 + mt * 16 + g;                                        \
        uint32_t ah[4];                                                       \
        ah[0] = (ASBUF)[r * 8 + t];                                           \
        ah[1] = (ASBUF)[(r + 8) * 8 + t];                                     \
        ah[2] = (ASBUF)[r * 8 + t + 4];                                       \
        ah[3] = (ASBUF)[(r + 8) * 8 + t + 4];                                 \
        _Pragma("unroll")                                                     \
        for (int nt = 0; nt < 4; nt++)                                        \
            mma16816(acc[mt][nt], ah, bf[nt]);                                \
    }                                                                         \
}

#define MMA_EPILOGUE(DST, PSUM, PSQ, SS_SMEM, SQ_SMEM)                        \
{                                                                             \
    _Pragma("unroll")                                                         \
    for (int mt = 0; mt < 4; mt++) {                                          \
        _Pragma("unroll")                                                     \
        for (int nt = 0; nt < 4; nt++) {                                      \
            int row = i0 + wm * 64 + mt * 16 + g;                             \
            int col = j0 + wn * 32 + nt * 8 + 2 * t;                          \
            *(float2*)&(DST)[(size_t)row * MTOT + col] =                      \
                make_float2(acc[mt][nt][0], acc[mt][nt][1]);                  \
            *(float2*)&(DST)[(size_t)(row + 8) * MTOT + col] =                \
                make_float2(acc[mt][nt][2], acc[mt][nt][3]);                  \
        }                                                                     \
    }                                                                         \
    __syncthreads();                                                          \
    float* Ssum = (SS_SMEM);                                                  \
    float* Ssq  = (SQ_SMEM);                                                  \
    const int ci = wn * 4 + t;                                                \
    _Pragma("unroll")                                                         \
    for (int mt = 0; mt < 4; mt++) {                                          \
        int r0 = wm * 64 + mt * 16 + g;                                       \
        float s0 = 0.f, q0 = 0.f, s1 = 0.f, q1 = 0.f;                         \
        _Pragma("unroll")                                                     \
        for (int nt = 0; nt < 4; nt++) {                                      \
            float e0 = acc[mt][nt][0], e1 = acc[mt][nt][1];                   \
            float e2 = acc[mt][nt][2], e3 = acc[mt][nt][3];                   \
            s0 += e0 + e1;  q0 += e0 * e0 + e1 * e1;                          \
            s1 += e2 + e3;  q1 += e2 * e2 + e3 * e3;                          \
        }                                                                     \
        Ssum[ci * 128 + r0]     = s0;  Ssq[ci * 128 + r0]     = q0;           \
        Ssum[ci * 128 + r0 + 8] = s1;  Ssq[ci * 128 + r0 + 8] = q1;           \
    }                                                                         \
    __syncthreads();                                                          \
    if (tid < 128) {                                                          \
        float s = 0.f;                                                        \
        _Pragma("unroll")                                                     \
        for (int c = 0; c < 16; c++) s += Ssum[c * 128 + tid];                \
        (PSUM)[(size_t)(i0 + tid) * GRIDX + blockIdx.x] = s;                  \
    } else {                                                                  \
        int r = tid - 128;                                                    \
        float q = 0.f;                                                        \
        _Pragma("unroll")                                                     \
        for (int c = 0; c < 16; c++) q += Ssq[c * 128 + r];                   \
        (PSQ)[(size_t)(i0 + r) * GRIDX + blockIdx.x] = q;                     \
    }                                                                         \
}

// ---------------------------------------------------------------------------
// Kernel 3a: GEMM1 — fp16 mma, 4-stage cp.async pipeline, pure-copy operands.
//   H1 = W1 @ [skip ; interp], K=384 (24 k-steps). B comes pre-packed from
//   g_BP1, so both tile loads are bare 16B cp.async ops (no ALU, no regs).
// ---------------------------------------------------------------------------
__global__ void __launch_bounds__(256) gemm1_kernel()
{
    __shared__ uint32_t As[4][128 * 8];   // [m][kpair]        4 KB/stage
    __shared__ uint32_t Bs[4][8 * 128];   // [kpair][n ^ swz]  4 KB/stage

    const int tid  = threadIdx.x;
    const int lane = tid & 31;
    const int wid  = tid >> 5;
    const int wm   = wid >> 2;
    const int wn   = wid & 3;
    const int g    = lane >> 2;
    const int t    = lane & 3;

    const int j0 = blockIdx.x * 128;
    const int i0 = blockIdx.y * 128;

    const int arow = tid >> 1;
    const int akh  = tid & 1;
    const int brp  = tid >> 5;
    const int bc0  = lane * 4;

    // per-thread fixed smem dst addresses (stage 0); stages offset by 4KB
    const uint32_t a_dst0 = (uint32_t)__cvta_generic_to_shared(&As[0][arow * 8 + akh * 4]);
    const uint32_t b_dst0 = (uint32_t)__cvta_generic_to_shared(&Bs[0][brp * 128 + (bc0 ^ (brp << 3))]);
    const __half*   a_src0 = g_W1h + (size_t)(i0 + arow) * C1 + akh * 8;
    const uint32_t* b_src0 = g_BP1 + (size_t)brp * MTOT + j0 + bc0;

    float acc[4][4][4];
    #pragma unroll
    for (int mt = 0; mt < 4; mt++)
        #pragma unroll
        for (int nt = 0; nt < 4; nt++)
            #pragma unroll
            for (int e = 0; e < 4; e++) acc[mt][nt][e] = 0.0f;

    #define G1_ISSUE(step)                                                    \
    {                                                                         \
        int s_ = (step) & 3;                                                  \
        cp_async16(a_dst0 + s_ * 4096, a_src0 + (step) * 16);                 \
        cp_async16(b_dst0 + s_ * 4096, b_src0 + (size_t)(step) * 8 * MTOT);   \
        CP_COMMIT();                                                          \
    }

    G1_ISSUE(0); G1_ISSUE(1); G1_ISSUE(2);

    #pragma unroll 1
    for (int i = 0; i < 21; i++) {
        CP_WAIT(2);
        __syncthreads();
        G1_ISSUE(i + 3);
        MMA_COMPUTE(As[i & 3], Bs[i & 3]);
    }
    CP_WAIT(2); __syncthreads(); MMA_COMPUTE(As[21 & 3], Bs[21 & 3]);
    CP_WAIT(1); __syncthreads(); MMA_COMPUTE(As[22 & 3], Bs[22 & 3]);
    CP_WAIT(0); __syncthreads(); MMA_COMPUTE(As[23 & 3], Bs[23 & 3]);

    MMA_EPILOGUE(g_h1, g_psA, g_pqA, (float*)As, (float*)Bs);
    #undef G1_ISSUE
}

// ---------------------------------------------------------------------------
// Kernel 3b: GEMM2 — proven 2-stage register-prefetch path (R7/299.5 config).
//   H2 = W2 @ relu(BN1(H1)), K=256; BN1 apply fused into the B loader.
// ---------------------------------------------------------------------------
__global__ void __launch_bounds__(256, 2) gemm2_kernel()
{
    __shared__ uint32_t As[2][128 * 8];
    __shared__ uint32_t Bs[2][8 * 128];

    const int tid  = threadIdx.x;
    const int lane = tid & 31;
    const int wid  = tid >> 5;
    const int wm   = wid >> 2;
    const int wn   = wid & 3;
    const int g    = lane >> 2;
    const int t    = lane & 3;

    const int j0 = blockIdx.x * 128;
    const int i0 = blockIdx.y * 128;

    const int arow = tid >> 1;
    const int akh  = tid & 1;
    const int brp  = tid >> 5;
    const int bc0  = lane * 4;

    float acc[4][4][4];
    #pragma unroll
    for (int mt = 0; mt < 4; mt++)
        #pragma unroll
        for (int nt = 0; nt < 4; nt++)
            #pragma unroll
            for (int e = 0; e < 4; e++) acc[mt][nt][e] = 0.0f;

    uint4 ra;
    uint32_t pB[4];

    #define G2_LDG(kt)                                                        \
    {                                                                         \
        ra = *(const uint4*)(g_W2h + (size_t)(i0 + arow) * C2 + (kt) + akh * 8); \
        int k0 = (kt) + brp * 2;                                              \
        const float* s0 = g_h1 + (size_t)k0 * MTOT + j0 + bc0;                \
        float4 rb0 = *(const float4*)s0;                                      \
        float4 rb1 = *(const float4*)(s0 + MTOT);                             \
        float2 q0 = g_ss1[k0], q1 = g_ss1[k0 + 1];                            \
        const float* x0 = &rb0.x; const float* x1 = &rb1.x;                   \
        _Pragma("unroll")                                                     \
        for (int e = 0; e < 4; e++) {                                         \
            float u0 = fmaxf(fmaf(x0[e], q0.x, q0.y), 0.0f);                  \
            float u1 = fmaxf(fmaf(x1[e], q1.x, q1.y), 0.0f);                  \
            __half2 h = __floats2half2_rn(u0, u1);                            \
            pB[e] = *reinterpret_cast<uint32_t*>(&h);                         \
        }                                                                     \
    }

    #define G2_STS(buf)                                                       \
    {                                                                         \
        *(uint4*)&As[buf][arow * 8 + akh * 4] = ra;                           \
        int col = bc0 ^ (brp << 3);                                           \
        *(uint4*)&Bs[buf][brp * 128 + col] = *(uint4*)pB;                     \
    }

    G2_LDG(0);
    G2_STS(0);
    __syncthreads();

    int buf = 0;
    for (int kt = 16; kt < C2; kt += 16) {
        G2_LDG(kt);
        MMA_COMPUTE(As[buf], Bs[buf]);
        G2_STS(buf ^ 1);
        __syncthreads();
        buf ^= 1;
    }
    MMA_COMPUTE(As[buf], Bs[buf]);

    MMA_EPILOGUE(g_h2, g_psB, g_pqB, (float*)As, (float*)Bs);
    #undef G2_LDG
    #undef G2_STS
}

// ---------------------------------------------------------------------------
// Kernel 4: reduce per-block partials -> per-channel (scale, shift).
// ---------------------------------------------------------------------------
__global__ void __launch_bounds__(256) bn_reduce_kernel(
    const float* __restrict__ g, const float* __restrict__ beta, int which)
{
    const int c   = blockIdx.x;
    const int tid = threadIdx.x;
    const float* ps = (which == 1) ? g_psA : g_psB;
    const float* pq = (which == 1) ? g_pqA : g_pqB;

    double s = (double)ps[(size_t)c * GRIDX + tid] + (double)ps[(size_t)c * GRIDX + tid + 256];
    double q = (double)pq[(size_t)c * GRIDX + tid] + (double)pq[(size_t)c * GRIDX + tid + 256];

    __shared__ double r1[256], r2[256];
    r1[tid] = s;  r2[tid] = q;
    __syncthreads();
    for (int o = 128; o > 0; o >>= 1) {
        if (tid < o) { r1[tid] += r1[tid + o]; r2[tid] += r2[tid + o]; }
        __syncthreads();
    }
    if (tid == 0) {
        double mean = r1[0] / (double)MTOT;
        double var  = r2[0] / (double)MTOT - mean * mean;
        double rs   = 1.0 / sqrt(var + 1e-5);
        float scale = (float)((double)g[c] * rs);
        float shift = (float)((double)beta[c] - mean * (double)g[c] * rs);
        if (which == 1) g_ss1[c] = make_float2(scale, shift);
        else            g_ss2[c] = make_float2(scale, shift);
    }
}

// ---------------------------------------------------------------------------
// Kernel 5: final BN2 + ReLU + layout transform [c][b*N+n] -> [b][c][n]
// ---------------------------------------------------------------------------
__global__ void __launch_bounds__(256) bn_out_kernel(float* __restrict__ out)
{
    size_t f = (size_t)blockIdx.x * blockDim.x + threadIdx.x;
    size_t e = f * 4;
    int c = (int)(e / MTOT);
    int m = (int)(e % MTOT);
    int b = m / NPTS;
    int n = m % NPTS;

    float4 v = ((const float4*)g_h2)[f];
    float2 ss = g_ss2[c];
    v.x = fmaxf(fmaf(v.x, ss.x, ss.y), 0.0f);
    v.y = fmaxf(fmaf(v.y, ss.x, ss.y), 0.0f);
    v.z = fmaxf(fmaf(v.z, ss.x, ss.y), 0.0f);
    v.w = fmaxf(fmaf(v.w, ss.x, ss.y), 0.0f);
    *(float4*)(out + ((size_t)b * C3 + c) * NPTS + n) = v;
}

// ---------------------------------------------------------------------------
// Launcher
// ---------------------------------------------------------------------------
extern "C" void kernel_launch(void* const* d_in, const int* in_sizes, int n_in,
                              void* d_out, int out_size)
{
    const float* pp    = (const float*)d_in[0];
    const float* spp   = (const float*)d_in[1];
    const float* skip  = (const float*)d_in[2];
    const float* sfeat = (const float*)d_in[3];
    const float* W1    = (const float*)d_in[4];
    // d_in[5] = b1 (cancels inside BN)
    const float* g1    = (const float*)d_in[6];
    const float* be1   = (const float*)d_in[7];
    const float* W2    = (const float*)d_in[8];
    // d_in[9] = b2 (cancels inside BN)
    const float* g2    = (const float*)d_in[10];
    const float* be2   = (const float*)d_in[11];
    float* out = (float*)d_out;

    prep_weights_kernel<<<(C2 * C1 + 255) / 256, 256>>>(W1, W2);
    {
        dim3 grid(MTOT / 1024, D1 / 2);
        pack_skip_kernel<<<grid, 256>>>(skip);
    }

    knn_kernel<<<B_ * (NPTS / 256), 128>>>(pp, spp);
    {
        dim3 grid(NS / 32, D2 / 32, B_), blk(32, 8);
        transpose_sfeat_kernel<<<grid, blk>>>(sfeat);
    }

    interp_kernel<<<MTOT / 32, 256>>>();

    {   // GEMM1 (+BN1 partials): H1 = W1 @ [skip ; interp]
        dim3 grid(GRIDX, C2 / 128);
        gemm1_kernel<<<grid, 256>>>();
    }
    bn_reduce_kernel<<<C2, 256>>>(g1, be1, 1);

    {   // GEMM2 (+BN2 partials): H2 = W2 @ relu(BN1(H1))
        dim3 grid(GRIDX, C3 / 128);
        gemm2_kernel<<<grid, 256>>>();
    }
    bn_reduce_kernel<<<C3, 256>>>(g2, be2, 2);

    bn_out_kernel<<<(C3 * MTOT / 4) / 256, 256>>>(out);
}